// round 1
// baseline (speedup 1.0000x reference)
#include <cuda_runtime.h>
#include <math.h>

#define T_LEN 16384
#define NB 4

static __device__ __forceinline__ float sigmoidf_(float v) {
    return 1.0f / (1.0f + __expf(-v));
}

#define SQRT_HALF_F 0.70710678118654752f

// ---------------- scratch (allocation-free: __device__ globals) ----------------
__device__ float g_h[2][NB * 64 * T_LEN];     // residual ping-pong
__device__ float g_z[NB * 64 * T_LEN];        // gated activations per layer
__device__ float g_skip[NB * 256 * T_LEN];    // skip accumulator
__device__ float g_tmp[NB * 256 * T_LEN];     // final intermediate

// =======================================================================
// Kernel 1: first conv (k=2 causal, 256 -> 64) + tanh.  Persistent blocks.
// SMEM: Wf [ic][k][oc] 32768 f, bias 64 f, Xs [ic][68] 17408 f  => 200960 B
// =======================================================================
#define FIRST_SMEM 200960
__global__ __launch_bounds__(256) void first_kernel(
    const float* __restrict__ x, const float* __restrict__ Wf,
    const float* __restrict__ bf)
{
    extern __shared__ float sm[];
    float* Wf_s = sm;              // ic*128 + k*64 + oc
    float* bs   = Wf_s + 32768;    // 64
    float* Xs   = bs + 64;         // ic*68 + jj  (jj 0..63 = t0+jj, jj==64 = t0-1)

    int tid = threadIdx.x;
    for (int i = tid; i < 64 * 256 * 2; i += 256) {
        int oc = i >> 9; int ic = (i >> 1) & 255; int k = i & 1;
        Wf_s[ic * 128 + k * 64 + oc] = Wf[i];
    }
    if (tid < 64) bs[tid] = bf[tid];
    __syncthreads();

    int tq = tid & 7, grp = tid >> 3;
    int tb = tq * 8, oc2 = grp * 2;

    for (int tile = blockIdx.x; tile < NB * 256; tile += gridDim.x) {
        int b = tile >> 8;
        int t0 = (tile & 255) << 6;
        __syncthreads();
        for (int i = tid; i < 256 * 65; i += 256) {
            int ic = i / 65, jj = i - ic * 65;
            int t = (jj < 64) ? (t0 + jj) : (t0 - 1);
            Xs[ic * 68 + jj] = (t >= 0) ? x[((b * 256 + ic) << 14) + t] : 0.f;
        }
        __syncthreads();

        float acc[2][8];
#pragma unroll
        for (int a = 0; a < 2; a++)
#pragma unroll
            for (int j = 0; j < 8; j++) acc[a][j] = 0.f;

#pragma unroll 2
        for (int ic = 0; ic < 256; ic++) {
            const float* xp = Xs + ic * 68 + tb;
            float4 x0 = *(const float4*)xp;
            float4 x1 = *(const float4*)(xp + 4);
            float xm1 = (tb == 0) ? Xs[ic * 68 + 64] : Xs[ic * 68 + tb - 1];
            float2 w0 = *(const float2*)(Wf_s + ic * 128 + oc2);
            float2 w1 = *(const float2*)(Wf_s + ic * 128 + 64 + oc2);
            float xc[8] = {x0.x, x0.y, x0.z, x0.w, x1.x, x1.y, x1.z, x1.w};
            float xpv[8] = {xm1, xc[0], xc[1], xc[2], xc[3], xc[4], xc[5], xc[6]};
            float wa[2] = {w0.x, w0.y};
            float wb[2] = {w1.x, w1.y};
#pragma unroll
            for (int a = 0; a < 2; a++)
#pragma unroll
                for (int j = 0; j < 8; j++)
                    acc[a][j] += wa[a] * xpv[j] + wb[a] * xc[j];
        }

#pragma unroll
        for (int a = 0; a < 2; a++) {
            int oc = oc2 + a;
            float bv = bs[oc];
            float* hp = &g_h[0][((b * 64 + oc) << 14) + t0 + tb];
            float4 v0, v1;
            v0.x = tanhf(acc[a][0] + bv); v0.y = tanhf(acc[a][1] + bv);
            v0.z = tanhf(acc[a][2] + bv); v0.w = tanhf(acc[a][3] + bv);
            v1.x = tanhf(acc[a][4] + bv); v1.y = tanhf(acc[a][5] + bv);
            v1.z = tanhf(acc[a][6] + bv); v1.w = tanhf(acc[a][7] + bv);
            *(float4*)hp = v0;
            *(float4*)(hp + 4) = v1;
        }
    }
}

// =======================================================================
// Kernel 2: per-layer gate:  y = Wdil * h(im2col, dilated) + Wc * c + b
//           z = tanh(y[0:64]) * sigmoid(y[64:128])  -> g_z
// SMEM: Wd[r][k][g] 24576, Wc[ci][g] 10240, bias 128,
//       Hs[k][r][t] 12288 (reused as Ys[t][g] stride 132), Cs[ci][t] 5120
//  => 52352 floats = 209408 B
// =======================================================================
#define GATE_SMEM 209408
__global__ __launch_bounds__(256) void gate_kernel(
    int layer, int dil, int hsel,
    const float* __restrict__ c,
    const float* __restrict__ W_dil, const float* __restrict__ b_dil,
    const float* __restrict__ W_c, const float* __restrict__ b_c)
{
    extern __shared__ float sm[];
    float* Wd_s = sm;                    // r*384 + k*128 + g
    float* Wc_s = Wd_s + 64 * 384;       // ci*128 + g
    float* bs   = Wc_s + 80 * 128;       // 128
    float* Hs   = bs + 128;              // k*4096 + r*64 + t
    float* Cs   = Hs + 12288;            // ci*64 + t
    float* Ys   = Hs;                    // [t][g] stride 132 (overlay)

    int tid = threadIdx.x;
    const float* Wd = W_dil + layer * 128 * 64 * 3;
    const float* Wc = W_c + layer * 128 * 80;
    const float* h_in = g_h[hsel];

    for (int i = tid; i < 128 * 64 * 3; i += 256) {
        int g = i / 192; int rem = i - g * 192; int r = rem / 3; int k = rem - r * 3;
        Wd_s[r * 384 + k * 128 + g] = Wd[i];
    }
    for (int i = tid; i < 128 * 80; i += 256) {
        int g = i / 80; int ci = i - g * 80;
        Wc_s[ci * 128 + g] = Wc[i];
    }
    if (tid < 128) bs[tid] = b_dil[layer * 128 + tid] + b_c[layer * 128 + tid];
    __syncthreads();

    int gq = tid & 31, warp = tid >> 5;
    int g4 = gq * 4, tb = warp * 8;

    for (int tile = blockIdx.x; tile < NB * 256; tile += gridDim.x) {
        int b = tile >> 8;
        int t0 = (tile & 255) << 6;
        __syncthreads();
        for (int i = tid; i < 3 * 64 * 64; i += 256) {
            int k = i >> 12; int r = (i >> 6) & 63; int j = i & 63;
            int t = t0 + j - (2 - k) * dil;
            Hs[i] = (t >= 0) ? h_in[((b * 64 + r) << 14) + t] : 0.f;
        }
        for (int i = tid; i < 80 * 64; i += 256) {
            int ci = i >> 6; int j = i & 63;
            Cs[i] = c[((b * 80 + ci) << 14) + t0 + j];
        }
        __syncthreads();

        float acc[4][8];
#pragma unroll
        for (int a = 0; a < 4; a++)
#pragma unroll
            for (int j = 0; j < 8; j++) acc[a][j] = 0.f;

#pragma unroll 2
        for (int r = 0; r < 64; r++) {
            const float* wp = Wd_s + r * 384 + g4;
            float4 w0 = *(const float4*)(wp);
            float4 w1 = *(const float4*)(wp + 128);
            float4 w2 = *(const float4*)(wp + 256);
            const float* hp = Hs + r * 64 + tb;
            float4 hA0 = *(const float4*)(hp);
            float4 hA1 = *(const float4*)(hp + 4);
            float4 hB0 = *(const float4*)(hp + 4096);
            float4 hB1 = *(const float4*)(hp + 4100);
            float4 hC0 = *(const float4*)(hp + 8192);
            float4 hC1 = *(const float4*)(hp + 8196);
            float wa[4] = {w0.x, w0.y, w0.z, w0.w};
            float wb[4] = {w1.x, w1.y, w1.z, w1.w};
            float wcv[4] = {w2.x, w2.y, w2.z, w2.w};
            float h0[8] = {hA0.x, hA0.y, hA0.z, hA0.w, hA1.x, hA1.y, hA1.z, hA1.w};
            float h1[8] = {hB0.x, hB0.y, hB0.z, hB0.w, hB1.x, hB1.y, hB1.z, hB1.w};
            float h2[8] = {hC0.x, hC0.y, hC0.z, hC0.w, hC1.x, hC1.y, hC1.z, hC1.w};
#pragma unroll
            for (int a = 0; a < 4; a++)
#pragma unroll
                for (int j = 0; j < 8; j++)
                    acc[a][j] += wa[a] * h0[j] + wb[a] * h1[j] + wcv[a] * h2[j];
        }

#pragma unroll 2
        for (int ci = 0; ci < 80; ci++) {
            float4 w = *(const float4*)(Wc_s + ci * 128 + g4);
            const float* cp = Cs + ci * 64 + tb;
            float4 c0 = *(const float4*)cp;
            float4 c1 = *(const float4*)(cp + 4);
            float wv[4] = {w.x, w.y, w.z, w.w};
            float cv[8] = {c0.x, c0.y, c0.z, c0.w, c1.x, c1.y, c1.z, c1.w};
#pragma unroll
            for (int a = 0; a < 4; a++)
#pragma unroll
                for (int j = 0; j < 8; j++)
                    acc[a][j] += wv[a] * cv[j];
        }

        __syncthreads();   // all Hs reads done -> safe to overlay Ys
#pragma unroll
        for (int j = 0; j < 8; j++) {
            float4 v;
            v.x = acc[0][j] + bs[g4 + 0];
            v.y = acc[1][j] + bs[g4 + 1];
            v.z = acc[2][j] + bs[g4 + 2];
            v.w = acc[3][j] + bs[g4 + 3];
            *(float4*)(Ys + (tb + j) * 132 + g4) = v;
        }
        __syncthreads();

        for (int i = tid; i < 64 * 64; i += 256) {
            int gz = i >> 6; int j = i & 63;
            float a = Ys[j * 132 + gz];
            float bgate = Ys[j * 132 + 64 + gz];
            float zv = tanhf(a) * sigmoidf_(bgate);
            g_z[((b * 64 + gz) << 14) + t0 + j] = zv;
        }
    }
}

// =======================================================================
// Kernel 3: per-layer skip + out:
//   s = Wskip @ z + bsk ;  skip accumulate (sqrt-half rule)
//   h' = (Wout @ z + bo + h) * sqrt(1/2)
// SMEM: Wsk[r][sc] 16384, Wo[r][oc] 4096, bsk 256, bo 64, Zs[r][t] 4096
//  => 24896 floats = 99584 B
// =======================================================================
#define SKIPOUT_SMEM 99584
__global__ __launch_bounds__(256) void skipout_kernel(
    int layer, int hsel,
    const float* __restrict__ W_skip, const float* __restrict__ b_skip,
    const float* __restrict__ W_out, const float* __restrict__ b_out)
{
    extern __shared__ float sm[];
    float* Wsk_s = sm;                  // r*256 + sc
    float* Wo_s  = Wsk_s + 16384;       // r*64 + oc
    float* bsk_s = Wo_s + 4096;         // 256
    float* bo_s  = bsk_s + 256;         // 64
    float* Zs    = bo_s + 64;           // r*64 + t

    int tid = threadIdx.x;
    const float* Wsk = W_skip + layer * 256 * 64;
    const float* Wo  = W_out + layer * 64 * 64;
    const float* h_in = g_h[hsel];
    float* h_out = g_h[1 - hsel];

    for (int i = tid; i < 256 * 64; i += 256) {
        int sc = i >> 6; int r = i & 63;
        Wsk_s[r * 256 + sc] = Wsk[i];
    }
    for (int i = tid; i < 64 * 64; i += 256) {
        int oc = i >> 6; int r = i & 63;
        Wo_s[r * 64 + oc] = Wo[i];
    }
    if (tid < 256) bsk_s[tid] = b_skip[layer * 256 + tid];
    if (tid < 64)  bo_s[tid]  = b_out[layer * 64 + tid];
    __syncthreads();

    int tq = tid & 7, grp = tid >> 3;
    int tb = tq * 8;
    int sc8 = grp * 8;
    int oc2 = grp * 2;

    for (int tile = blockIdx.x; tile < NB * 256; tile += gridDim.x) {
        int b = tile >> 8;
        int t0 = (tile & 255) << 6;
        __syncthreads();
        for (int i = tid; i < 4096; i += 256) {
            int r = i >> 6; int j = i & 63;
            Zs[i] = g_z[((b * 64 + r) << 14) + t0 + j];
        }
        __syncthreads();

        float accS[8][8];
        float accO[2][8];
#pragma unroll
        for (int a = 0; a < 8; a++)
#pragma unroll
            for (int j = 0; j < 8; j++) accS[a][j] = 0.f;
#pragma unroll
        for (int a = 0; a < 2; a++)
#pragma unroll
            for (int j = 0; j < 8; j++) accO[a][j] = 0.f;

#pragma unroll 2
        for (int r = 0; r < 64; r++) {
            const float* zp = Zs + r * 64 + tb;
            float4 z0 = *(const float4*)zp;
            float4 z1 = *(const float4*)(zp + 4);
            float zv[8] = {z0.x, z0.y, z0.z, z0.w, z1.x, z1.y, z1.z, z1.w};
            float4 wA = *(const float4*)(Wsk_s + r * 256 + sc8);
            float4 wB = *(const float4*)(Wsk_s + r * 256 + sc8 + 4);
            float ws[8] = {wA.x, wA.y, wA.z, wA.w, wB.x, wB.y, wB.z, wB.w};
            float2 wo = *(const float2*)(Wo_s + r * 64 + oc2);
#pragma unroll
            for (int a = 0; a < 8; a++)
#pragma unroll
                for (int j = 0; j < 8; j++)
                    accS[a][j] += ws[a] * zv[j];
#pragma unroll
            for (int j = 0; j < 8; j++) {
                accO[0][j] += wo.x * zv[j];
                accO[1][j] += wo.y * zv[j];
            }
        }

        // skip accumulate
#pragma unroll
        for (int a = 0; a < 8; a++) {
            int sc = sc8 + a;
            float bsv = bsk_s[sc];
            float* sp = &g_skip[((b * 256 + sc) << 14) + t0 + tb];
            if (layer == 0) {
                float4 v0 = make_float4(accS[a][0] + bsv, accS[a][1] + bsv,
                                        accS[a][2] + bsv, accS[a][3] + bsv);
                float4 v1 = make_float4(accS[a][4] + bsv, accS[a][5] + bsv,
                                        accS[a][6] + bsv, accS[a][7] + bsv);
                *(float4*)sp = v0;
                *(float4*)(sp + 4) = v1;
            } else {
                float4 o0 = *(const float4*)sp;
                float4 o1 = *(const float4*)(sp + 4);
                float4 v0, v1;
                v0.x = (o0.x + accS[a][0] + bsv) * SQRT_HALF_F;
                v0.y = (o0.y + accS[a][1] + bsv) * SQRT_HALF_F;
                v0.z = (o0.z + accS[a][2] + bsv) * SQRT_HALF_F;
                v0.w = (o0.w + accS[a][3] + bsv) * SQRT_HALF_F;
                v1.x = (o1.x + accS[a][4] + bsv) * SQRT_HALF_F;
                v1.y = (o1.y + accS[a][5] + bsv) * SQRT_HALF_F;
                v1.z = (o1.z + accS[a][6] + bsv) * SQRT_HALF_F;
                v1.w = (o1.w + accS[a][7] + bsv) * SQRT_HALF_F;
                *(float4*)sp = v0;
                *(float4*)(sp + 4) = v1;
            }
        }

        // residual update
#pragma unroll
        for (int a = 0; a < 2; a++) {
            int oc = oc2 + a;
            float bov = bo_s[oc];
            const float* hip = h_in + ((b * 64 + oc) << 14) + t0 + tb;
            float* hop = h_out + ((b * 64 + oc) << 14) + t0 + tb;
            float4 h0 = *(const float4*)hip;
            float4 h1 = *(const float4*)(hip + 4);
            float4 v0, v1;
            v0.x = (accO[a][0] + bov + h0.x) * SQRT_HALF_F;
            v0.y = (accO[a][1] + bov + h0.y) * SQRT_HALF_F;
            v0.z = (accO[a][2] + bov + h0.z) * SQRT_HALF_F;
            v0.w = (accO[a][3] + bov + h0.w) * SQRT_HALF_F;
            v1.x = (accO[a][4] + bov + h1.x) * SQRT_HALF_F;
            v1.y = (accO[a][5] + bov + h1.y) * SQRT_HALF_F;
            v1.z = (accO[a][6] + bov + h1.z) * SQRT_HALF_F;
            v1.w = (accO[a][7] + bov + h1.w) * SQRT_HALF_F;
            *(float4*)hop = v0;
            *(float4*)(hop + 4) = v1;
        }
    }
}

// =======================================================================
// Kernel 4: dense 256x256 over time (final 1x1 convs).
// stage 0: g_tmp = relu(W1 @ relu(g_skip) + b1)
// stage 1: out   = W2 @ g_tmp + b2
// SMEM: Ss[sc][t] 16384, Wt[scc][oc] stride 260 = 16640, bias 256 => 133120 B
// =======================================================================
#define DENSE_SMEM 133120
__global__ __launch_bounds__(256) void dense256_kernel(
    int stage, float* __restrict__ final_out,
    const float* __restrict__ W, const float* __restrict__ bias)
{
    extern __shared__ float sm[];
    float* Ss = sm;             // sc*64 + t
    float* Wt = Ss + 16384;     // scc*260 + oc
    float* bb = Wt + 16640;     // 256

    const float* in = (stage == 0) ? g_skip : g_tmp;
    float* out = (stage == 0) ? g_tmp : final_out;

    int tid = threadIdx.x;
    int b = blockIdx.x >> 8;
    int t0 = (blockIdx.x & 255) << 6;

    if (tid < 256) bb[tid] = bias[tid];
    for (int i = tid; i < 16384; i += 256) {
        int sc = i >> 6, j = i & 63;
        float v = in[((b * 256 + sc) << 14) + t0 + j];
        if (stage == 0) v = fmaxf(v, 0.f);
        Ss[i] = v;
    }

    int tq = tid & 7, ocg = tid >> 3;
    int tb = tq * 8, oc8 = ocg * 8;

    float acc[8][8];
#pragma unroll
    for (int a = 0; a < 8; a++)
#pragma unroll
        for (int j = 0; j < 8; j++) acc[a][j] = 0.f;

    for (int c0 = 0; c0 < 256; c0 += 64) {
        __syncthreads();   // also covers initial Ss/bb stores on first iter
        for (int i = tid; i < 64 * 256; i += 256) {
            int scc = i & 63, oc = i >> 6;
            Wt[scc * 260 + oc] = W[oc * 256 + c0 + scc];
        }
        __syncthreads();
#pragma unroll 2
        for (int scc = 0; scc < 64; scc++) {
            const float* sp = Ss + (c0 + scc) * 64 + tb;
            float4 z0 = *(const float4*)sp;
            float4 z1 = *(const float4*)(sp + 4);
            float zv[8] = {z0.x, z0.y, z0.z, z0.w, z1.x, z1.y, z1.z, z1.w};
            float4 wA = *(const float4*)(Wt + scc * 260 + oc8);
            float4 wB = *(const float4*)(Wt + scc * 260 + oc8 + 4);
            float wv[8] = {wA.x, wA.y, wA.z, wA.w, wB.x, wB.y, wB.z, wB.w};
#pragma unroll
            for (int a = 0; a < 8; a++)
#pragma unroll
                for (int j = 0; j < 8; j++)
                    acc[a][j] += wv[a] * zv[j];
        }
    }

#pragma unroll
    for (int a = 0; a < 8; a++) {
        int oc = oc8 + a;
        float bv = bb[oc];
        float* op = out + ((b * 256 + oc) << 14) + t0 + tb;
        float4 v0 = make_float4(acc[a][0] + bv, acc[a][1] + bv,
                                acc[a][2] + bv, acc[a][3] + bv);
        float4 v1 = make_float4(acc[a][4] + bv, acc[a][5] + bv,
                                acc[a][6] + bv, acc[a][7] + bv);
        if (stage == 0) {
            v0.x = fmaxf(v0.x, 0.f); v0.y = fmaxf(v0.y, 0.f);
            v0.z = fmaxf(v0.z, 0.f); v0.w = fmaxf(v0.w, 0.f);
            v1.x = fmaxf(v1.x, 0.f); v1.y = fmaxf(v1.y, 0.f);
            v1.z = fmaxf(v1.z, 0.f); v1.w = fmaxf(v1.w, 0.f);
        }
        *(float4*)op = v0;
        *(float4*)(op + 4) = v1;
    }
}

// =======================================================================
extern "C" void kernel_launch(void* const* d_in, const int* in_sizes, int n_in,
                              void* d_out, int out_size)
{
    const float* x       = (const float*)d_in[0];
    const float* c       = (const float*)d_in[1];
    const float* W_first = (const float*)d_in[2];
    const float* b_first = (const float*)d_in[3];
    const float* W_dil   = (const float*)d_in[4];
    const float* b_dil   = (const float*)d_in[5];
    const float* W_c     = (const float*)d_in[6];
    const float* b_c     = (const float*)d_in[7];
    const float* W_skip  = (const float*)d_in[8];
    const float* b_skip  = (const float*)d_in[9];
    const float* W_out   = (const float*)d_in[10];
    const float* b_out   = (const float*)d_in[11];
    const float* W_last1 = (const float*)d_in[12];
    const float* b_last1 = (const float*)d_in[13];
    const float* W_last2 = (const float*)d_in[14];
    const float* b_last2 = (const float*)d_in[15];
    float* out = (float*)d_out;

    cudaFuncSetAttribute(first_kernel,  cudaFuncAttributeMaxDynamicSharedMemorySize, FIRST_SMEM);
    cudaFuncSetAttribute(gate_kernel,   cudaFuncAttributeMaxDynamicSharedMemorySize, GATE_SMEM);
    cudaFuncSetAttribute(skipout_kernel,cudaFuncAttributeMaxDynamicSharedMemorySize, SKIPOUT_SMEM);
    cudaFuncSetAttribute(dense256_kernel,cudaFuncAttributeMaxDynamicSharedMemorySize, DENSE_SMEM);

    int dev = 0;
    cudaGetDevice(&dev);
    int sm_count = 148;
    cudaDeviceGetAttribute(&sm_count, cudaDevAttrMultiProcessorCount, dev);
    int grid_p = sm_count < 1024 ? sm_count : 1024;

    first_kernel<<<grid_p, 256, FIRST_SMEM>>>(x, W_first, b_first);

    for (int l = 0; l < 20; l++) {
        int dil = 1 << (l % 10);
        int hsel = l & 1;   // layer l reads g_h[hsel], writes g_h[1-hsel]
        gate_kernel<<<grid_p, 256, GATE_SMEM>>>(l, dil, hsel, c,
                                                W_dil, b_dil, W_c, b_c);
        skipout_kernel<<<grid_p, 256, SKIPOUT_SMEM>>>(l, hsel,
                                                      W_skip, b_skip, W_out, b_out);
    }

    dense256_kernel<<<NB * 256, 256, DENSE_SMEM>>>(0, out, W_last1, b_last1);
    dense256_kernel<<<NB * 256, 256, DENSE_SMEM>>>(1, out, W_last2, b_last2);
}

// round 2
// speedup vs baseline: 1.1341x; 1.1341x over previous
#include <cuda_runtime.h>
#include <math.h>

#define T_LEN 16384
#define NB 4

static __device__ __forceinline__ float sigmoidf_(float v) {
    return 1.0f / (1.0f + __expf(-v));
}

#define SQRT_HALF_F 0.70710678118654752f

typedef unsigned long long ull;

// packed f32x2 helpers (sm_103a FFMA2 path — ptxas never auto-emits)
static __device__ __forceinline__ ull pack2(float v) {
    ull r;
    asm("mov.b64 %0, {%1, %1};" : "=l"(r) : "f"(v));
    return r;
}
static __device__ __forceinline__ void fma2(ull& d, ull a, ull b) {
    asm("fma.rn.f32x2 %0, %1, %2, %0;" : "+l"(d) : "l"(a), "l"(b));
}
static __device__ __forceinline__ float2 unpack2(ull v) {
    float2 r;
    asm("mov.b64 {%0, %1}, %2;" : "=f"(r.x), "=f"(r.y) : "l"(v));
    return r;
}

// ---------------- scratch (allocation-free: __device__ globals) ----------------
__device__ float g_h[2][NB * 64 * T_LEN];     // residual ping-pong
__device__ float g_z[NB * 64 * T_LEN];        // gated activations per layer
__device__ float g_skip[NB * 256 * T_LEN];    // skip accumulator
__device__ float g_tmp[NB * 256 * T_LEN];     // final intermediate

// =======================================================================
// Kernel 1: first conv (k=2 causal, 256 -> 64) + tanh.  Persistent blocks.
// (unchanged from R1 — small share of runtime)
// =======================================================================
#define FIRST_SMEM 200960
__global__ __launch_bounds__(256) void first_kernel(
    const float* __restrict__ x, const float* __restrict__ Wf,
    const float* __restrict__ bf)
{
    extern __shared__ float sm[];
    float* Wf_s = sm;              // ic*128 + k*64 + oc
    float* bs   = Wf_s + 32768;    // 64
    float* Xs   = bs + 64;         // ic*68 + jj

    int tid = threadIdx.x;
    for (int i = tid; i < 64 * 256 * 2; i += 256) {
        int oc = i >> 9; int ic = (i >> 1) & 255; int k = i & 1;
        Wf_s[ic * 128 + k * 64 + oc] = Wf[i];
    }
    if (tid < 64) bs[tid] = bf[tid];
    __syncthreads();

    int tq = tid & 7, grp = tid >> 3;
    int tb = tq * 8, oc2 = grp * 2;

    for (int tile = blockIdx.x; tile < NB * 256; tile += gridDim.x) {
        int b = tile >> 8;
        int t0 = (tile & 255) << 6;
        __syncthreads();
        for (int i = tid; i < 256 * 65; i += 256) {
            int ic = i / 65, jj = i - ic * 65;
            int t = (jj < 64) ? (t0 + jj) : (t0 - 1);
            Xs[ic * 68 + jj] = (t >= 0) ? x[((b * 256 + ic) << 14) + t] : 0.f;
        }
        __syncthreads();

        float acc[2][8];
#pragma unroll
        for (int a = 0; a < 2; a++)
#pragma unroll
            for (int j = 0; j < 8; j++) acc[a][j] = 0.f;

#pragma unroll 2
        for (int ic = 0; ic < 256; ic++) {
            const float* xp = Xs + ic * 68 + tb;
            float4 x0 = *(const float4*)xp;
            float4 x1 = *(const float4*)(xp + 4);
            float xm1 = (tb == 0) ? Xs[ic * 68 + 64] : Xs[ic * 68 + tb - 1];
            float2 w0 = *(const float2*)(Wf_s + ic * 128 + oc2);
            float2 w1 = *(const float2*)(Wf_s + ic * 128 + 64 + oc2);
            float xc[8] = {x0.x, x0.y, x0.z, x0.w, x1.x, x1.y, x1.z, x1.w};
            float xpv[8] = {xm1, xc[0], xc[1], xc[2], xc[3], xc[4], xc[5], xc[6]};
            float wa[2] = {w0.x, w0.y};
            float wb[2] = {w1.x, w1.y};
#pragma unroll
            for (int a = 0; a < 2; a++)
#pragma unroll
                for (int j = 0; j < 8; j++)
                    acc[a][j] += wa[a] * xpv[j] + wb[a] * xc[j];
        }

#pragma unroll
        for (int a = 0; a < 2; a++) {
            int oc = oc2 + a;
            float bv = bs[oc];
            float* hp = &g_h[0][((b * 64 + oc) << 14) + t0 + tb];
            float4 v0, v1;
            v0.x = tanhf(acc[a][0] + bv); v0.y = tanhf(acc[a][1] + bv);
            v0.z = tanhf(acc[a][2] + bv); v0.w = tanhf(acc[a][3] + bv);
            v1.x = tanhf(acc[a][4] + bv); v1.y = tanhf(acc[a][5] + bv);
            v1.z = tanhf(acc[a][6] + bv); v1.w = tanhf(acc[a][7] + bv);
            *(float4*)hp = v0;
            *(float4*)(hp + 4) = v1;
        }
    }
}

// =======================================================================
// Kernel 2 (v2): gate, 512 threads, FFMA2 packed over time pairs.
// Each thread: 2 gates x 8 t (4 f32x2 accumulators per gate).
// =======================================================================
#define GATE_SMEM 209408
__global__ __launch_bounds__(512) void gate_kernel(
    int layer, int dil, int hsel,
    const float* __restrict__ c,
    const float* __restrict__ W_dil, const float* __restrict__ b_dil,
    const float* __restrict__ W_c, const float* __restrict__ b_c)
{
    extern __shared__ float sm[];
    float* Wd_s = sm;                    // r*384 + k*128 + g
    float* Wc_s = Wd_s + 24576;          // ci*128 + g
    float* bs   = Wc_s + 10240;          // 128
    float* Hs   = bs + 128;              // k*4096 + r*64 + t
    float* Cs   = Hs + 12288;            // ci*64 + t
    float* Ys   = Hs;                    // [t][g] stride 132 (overlay)

    int tid = threadIdx.x;
    const float* Wd = W_dil + layer * 128 * 64 * 3;
    const float* Wc = W_c + layer * 128 * 80;
    const float* h_in = g_h[hsel];

    for (int i = tid; i < 128 * 64 * 3; i += 512) {
        int g = i / 192; int rem = i - g * 192; int r = rem / 3; int k = rem - r * 3;
        Wd_s[r * 384 + k * 128 + g] = Wd[i];
    }
    for (int i = tid; i < 128 * 80; i += 512) {
        int g = i / 80; int ci = i - g * 80;
        Wc_s[ci * 128 + g] = Wc[i];
    }
    if (tid < 128) bs[tid] = b_dil[layer * 128 + tid] + b_c[layer * 128 + tid];
    __syncthreads();

    int gq = tid & 63, tw = tid >> 6;
    int g2 = gq * 2, tb = tw * 8;

    for (int tile = blockIdx.x; tile < NB * 256; tile += gridDim.x) {
        int b = tile >> 8;
        int t0 = (tile & 255) << 6;
        __syncthreads();
        for (int i = tid; i < 3 * 64 * 64; i += 512) {
            int k = i >> 12; int r = (i >> 6) & 63; int j = i & 63;
            int t = t0 + j - (2 - k) * dil;
            Hs[i] = (t >= 0) ? h_in[((b * 64 + r) << 14) + t] : 0.f;
        }
        for (int i = tid; i < 80 * 64; i += 512) {
            int ci = i >> 6; int j = i & 63;
            Cs[i] = c[((b * 80 + ci) << 14) + t0 + j];
        }
        __syncthreads();

        ull acc[2][4];
#pragma unroll
        for (int a = 0; a < 2; a++)
#pragma unroll
            for (int p = 0; p < 4; p++) acc[a][p] = 0ull;

#pragma unroll 2
        for (int r = 0; r < 64; r++) {
            const float* wp = Wd_s + r * 384 + g2;
            float2 w0 = *(const float2*)(wp);
            float2 w1 = *(const float2*)(wp + 128);
            float2 w2 = *(const float2*)(wp + 256);
            ull wa0 = pack2(w0.x), wa1 = pack2(w0.y);
            ull wb0 = pack2(w1.x), wb1 = pack2(w1.y);
            ull wc0 = pack2(w2.x), wc1 = pack2(w2.y);
            const float* hp = Hs + r * 64 + tb;
            ulonglong2 hA0 = *(const ulonglong2*)(hp);
            ulonglong2 hA1 = *(const ulonglong2*)(hp + 4);
            ulonglong2 hB0 = *(const ulonglong2*)(hp + 4096);
            ulonglong2 hB1 = *(const ulonglong2*)(hp + 4100);
            ulonglong2 hC0 = *(const ulonglong2*)(hp + 8192);
            ulonglong2 hC1 = *(const ulonglong2*)(hp + 8196);
            ull h0[4] = {hA0.x, hA0.y, hA1.x, hA1.y};
            ull h1[4] = {hB0.x, hB0.y, hB1.x, hB1.y};
            ull h2[4] = {hC0.x, hC0.y, hC1.x, hC1.y};
#pragma unroll
            for (int p = 0; p < 4; p++) {
                fma2(acc[0][p], wa0, h0[p]);
                fma2(acc[1][p], wa1, h0[p]);
                fma2(acc[0][p], wb0, h1[p]);
                fma2(acc[1][p], wb1, h1[p]);
                fma2(acc[0][p], wc0, h2[p]);
                fma2(acc[1][p], wc1, h2[p]);
            }
        }

#pragma unroll 2
        for (int ci = 0; ci < 80; ci++) {
            float2 w = *(const float2*)(Wc_s + ci * 128 + g2);
            ull wa = pack2(w.x), wb = pack2(w.y);
            const float* cp = Cs + ci * 64 + tb;
            ulonglong2 c0 = *(const ulonglong2*)cp;
            ulonglong2 c1 = *(const ulonglong2*)(cp + 4);
            ull cv[4] = {c0.x, c0.y, c1.x, c1.y};
#pragma unroll
            for (int p = 0; p < 4; p++) {
                fma2(acc[0][p], wa, cv[p]);
                fma2(acc[1][p], wb, cv[p]);
            }
        }

        __syncthreads();   // all Hs reads done -> safe to overlay Ys
        {
            float ba0 = bs[g2], ba1 = bs[g2 + 1];
#pragma unroll
            for (int p = 0; p < 4; p++) {
                float2 ya = unpack2(acc[0][p]);
                float2 yb = unpack2(acc[1][p]);
                float2 ve = make_float2(ya.x + ba0, yb.x + ba1);
                float2 vo = make_float2(ya.y + ba0, yb.y + ba1);
                *(float2*)(Ys + (tb + 2 * p) * 132 + g2) = ve;
                *(float2*)(Ys + (tb + 2 * p + 1) * 132 + g2) = vo;
            }
        }
        __syncthreads();

        for (int i = tid; i < 64 * 64; i += 512) {
            int gz = i >> 6; int j = i & 63;
            float a = Ys[j * 132 + gz];
            float bgate = Ys[j * 132 + 64 + gz];
            float zv = tanhf(a) * sigmoidf_(bgate);
            g_z[((b * 64 + gz) << 14) + t0 + j] = zv;
        }
    }
}

// =======================================================================
// Kernel 3 (v2): skip + out, 512 threads, FFMA2.
// Each thread: 4 skip ch + 1 out ch, 8 t (4 f32x2 per channel).
// =======================================================================
#define SKIPOUT_SMEM 99584
__global__ __launch_bounds__(512) void skipout_kernel(
    int layer, int hsel,
    const float* __restrict__ W_skip, const float* __restrict__ b_skip,
    const float* __restrict__ W_out, const float* __restrict__ b_out)
{
    extern __shared__ float sm[];
    float* Wsk_s = sm;                  // r*256 + sc
    float* Wo_s  = Wsk_s + 16384;       // r*64 + oc
    float* bsk_s = Wo_s + 4096;         // 256
    float* bo_s  = bsk_s + 256;         // 64
    float* Zs    = bo_s + 64;           // r*64 + t

    int tid = threadIdx.x;
    const float* Wsk = W_skip + layer * 256 * 64;
    const float* Wo  = W_out + layer * 64 * 64;
    const float* h_in = g_h[hsel];
    float* h_out = g_h[1 - hsel];

    for (int i = tid; i < 256 * 64; i += 512) {
        int sc = i >> 6; int r = i & 63;
        Wsk_s[r * 256 + sc] = Wsk[i];
    }
    for (int i = tid; i < 64 * 64; i += 512) {
        int oc = i >> 6; int r = i & 63;
        Wo_s[r * 64 + oc] = Wo[i];
    }
    if (tid < 256) bsk_s[tid] = b_skip[layer * 256 + tid];
    if (tid < 64)  bo_s[tid]  = b_out[layer * 64 + tid];
    __syncthreads();

    int tq = tid & 7, grp = tid >> 3;   // grp 0..63
    int tb = tq * 8;
    int sc4 = grp * 4;
    int oc1 = grp;

    for (int tile = blockIdx.x; tile < NB * 256; tile += gridDim.x) {
        int b = tile >> 8;
        int t0 = (tile & 255) << 6;
        __syncthreads();
        for (int i = tid; i < 4096; i += 512) {
            int r = i >> 6; int j = i & 63;
            Zs[i] = g_z[((b * 64 + r) << 14) + t0 + j];
        }
        __syncthreads();

        ull accS[4][4];
        ull accO[4];
#pragma unroll
        for (int a = 0; a < 4; a++) {
            accO[a] = 0ull;
#pragma unroll
            for (int p = 0; p < 4; p++) accS[a][p] = 0ull;
        }

#pragma unroll 2
        for (int r = 0; r < 64; r++) {
            const float* zp = Zs + r * 64 + tb;
            ulonglong2 z0 = *(const ulonglong2*)zp;
            ulonglong2 z1 = *(const ulonglong2*)(zp + 4);
            ull zv[4] = {z0.x, z0.y, z1.x, z1.y};
            float4 ws = *(const float4*)(Wsk_s + r * 256 + sc4);
            ull w0 = pack2(ws.x), w1 = pack2(ws.y), w2 = pack2(ws.z), w3 = pack2(ws.w);
            ull wo = pack2(Wo_s[r * 64 + oc1]);
#pragma unroll
            for (int p = 0; p < 4; p++) {
                fma2(accS[0][p], w0, zv[p]);
                fma2(accS[1][p], w1, zv[p]);
                fma2(accS[2][p], w2, zv[p]);
                fma2(accS[3][p], w3, zv[p]);
                fma2(accO[p], wo, zv[p]);
            }
        }

        // skip accumulate
#pragma unroll
        for (int a = 0; a < 4; a++) {
            int sc = sc4 + a;
            float bsv = bsk_s[sc];
            float2 q0 = unpack2(accS[a][0]);
            float2 q1 = unpack2(accS[a][1]);
            float2 q2 = unpack2(accS[a][2]);
            float2 q3 = unpack2(accS[a][3]);
            float* sp = &g_skip[((b * 256 + sc) << 14) + t0 + tb];
            if (layer == 0) {
                float4 v0 = make_float4(q0.x + bsv, q0.y + bsv, q1.x + bsv, q1.y + bsv);
                float4 v1 = make_float4(q2.x + bsv, q2.y + bsv, q3.x + bsv, q3.y + bsv);
                *(float4*)sp = v0;
                *(float4*)(sp + 4) = v1;
            } else {
                float4 o0 = *(const float4*)sp;
                float4 o1 = *(const float4*)(sp + 4);
                float4 v0, v1;
                v0.x = (o0.x + q0.x + bsv) * SQRT_HALF_F;
                v0.y = (o0.y + q0.y + bsv) * SQRT_HALF_F;
                v0.z = (o0.z + q1.x + bsv) * SQRT_HALF_F;
                v0.w = (o0.w + q1.y + bsv) * SQRT_HALF_F;
                v1.x = (o1.x + q2.x + bsv) * SQRT_HALF_F;
                v1.y = (o1.y + q2.y + bsv) * SQRT_HALF_F;
                v1.z = (o1.z + q3.x + bsv) * SQRT_HALF_F;
                v1.w = (o1.w + q3.y + bsv) * SQRT_HALF_F;
                *(float4*)sp = v0;
                *(float4*)(sp + 4) = v1;
            }
        }

        // residual update (1 out channel per thread)
        {
            float bov = bo_s[oc1];
            float2 q0 = unpack2(accO[0]);
            float2 q1 = unpack2(accO[1]);
            float2 q2 = unpack2(accO[2]);
            float2 q3 = unpack2(accO[3]);
            const float* hip = h_in + ((b * 64 + oc1) << 14) + t0 + tb;
            float* hop = h_out + ((b * 64 + oc1) << 14) + t0 + tb;
            float4 h0 = *(const float4*)hip;
            float4 h1 = *(const float4*)(hip + 4);
            float4 v0, v1;
            v0.x = (q0.x + bov + h0.x) * SQRT_HALF_F;
            v0.y = (q0.y + bov + h0.y) * SQRT_HALF_F;
            v0.z = (q1.x + bov + h0.z) * SQRT_HALF_F;
            v0.w = (q1.y + bov + h0.w) * SQRT_HALF_F;
            v1.x = (q2.x + bov + h1.x) * SQRT_HALF_F;
            v1.y = (q2.y + bov + h1.y) * SQRT_HALF_F;
            v1.z = (q3.x + bov + h1.z) * SQRT_HALF_F;
            v1.w = (q3.y + bov + h1.w) * SQRT_HALF_F;
            *(float4*)hop = v0;
            *(float4*)(hop + 4) = v1;
        }
    }
}

// =======================================================================
// Kernel 4 (v2): dense 256x256, 512 threads, persistent, FFMA2.
// =======================================================================
#define DENSE_SMEM 133120
__global__ __launch_bounds__(512) void dense256_kernel(
    int stage, float* __restrict__ final_out,
    const float* __restrict__ W, const float* __restrict__ bias)
{
    extern __shared__ float sm[];
    float* Ss = sm;             // sc*64 + t
    float* Wt = Ss + 16384;     // scc*260 + oc
    float* bb = Wt + 16640;     // 256

    const float* in = (stage == 0) ? g_skip : g_tmp;
    float* out = (stage == 0) ? g_tmp : final_out;

    int tid = threadIdx.x;
    if (tid < 256) bb[tid] = bias[tid];

    int tq = tid & 7, ocg = tid >> 3;
    int tb = tq * 8, oc4 = ocg * 4;

    for (int tile = blockIdx.x; tile < NB * 256; tile += gridDim.x) {
        int b = tile >> 8;
        int t0 = (tile & 255) << 6;

        __syncthreads();
        for (int i = tid; i < 16384; i += 512) {
            int sc = i >> 6, j = i & 63;
            float v = in[((b * 256 + sc) << 14) + t0 + j];
            if (stage == 0) v = fmaxf(v, 0.f);
            Ss[i] = v;
        }

        ull acc[4][4];
#pragma unroll
        for (int a = 0; a < 4; a++)
#pragma unroll
            for (int p = 0; p < 4; p++) acc[a][p] = 0ull;

        for (int c0 = 0; c0 < 256; c0 += 64) {
            __syncthreads();   // covers Ss stores on first iter, Wt reuse after
            for (int i = tid; i < 64 * 256; i += 512) {
                int scc = i & 63, oc = i >> 6;
                Wt[scc * 260 + oc] = W[oc * 256 + c0 + scc];
            }
            __syncthreads();
#pragma unroll 2
            for (int scc = 0; scc < 64; scc++) {
                const float* sp = Ss + (c0 + scc) * 64 + tb;
                ulonglong2 z0 = *(const ulonglong2*)sp;
                ulonglong2 z1 = *(const ulonglong2*)(sp + 4);
                ull zv[4] = {z0.x, z0.y, z1.x, z1.y};
                float4 w = *(const float4*)(Wt + scc * 260 + oc4);
                ull w0 = pack2(w.x), w1 = pack2(w.y), w2 = pack2(w.z), w3 = pack2(w.w);
#pragma unroll
                for (int p = 0; p < 4; p++) {
                    fma2(acc[0][p], w0, zv[p]);
                    fma2(acc[1][p], w1, zv[p]);
                    fma2(acc[2][p], w2, zv[p]);
                    fma2(acc[3][p], w3, zv[p]);
                }
            }
        }

#pragma unroll
        for (int a = 0; a < 4; a++) {
            int oc = oc4 + a;
            float bv = bb[oc];
            float2 q0 = unpack2(acc[a][0]);
            float2 q1 = unpack2(acc[a][1]);
            float2 q2 = unpack2(acc[a][2]);
            float2 q3 = unpack2(acc[a][3]);
            float* op = out + ((b * 256 + oc) << 14) + t0 + tb;
            float4 v0 = make_float4(q0.x + bv, q0.y + bv, q1.x + bv, q1.y + bv);
            float4 v1 = make_float4(q2.x + bv, q2.y + bv, q3.x + bv, q3.y + bv);
            if (stage == 0) {
                v0.x = fmaxf(v0.x, 0.f); v0.y = fmaxf(v0.y, 0.f);
                v0.z = fmaxf(v0.z, 0.f); v0.w = fmaxf(v0.w, 0.f);
                v1.x = fmaxf(v1.x, 0.f); v1.y = fmaxf(v1.y, 0.f);
                v1.z = fmaxf(v1.z, 0.f); v1.w = fmaxf(v1.w, 0.f);
            }
            *(float4*)op = v0;
            *(float4*)(op + 4) = v1;
        }
    }
}

// =======================================================================
extern "C" void kernel_launch(void* const* d_in, const int* in_sizes, int n_in,
                              void* d_out, int out_size)
{
    const float* x       = (const float*)d_in[0];
    const float* c       = (const float*)d_in[1];
    const float* W_first = (const float*)d_in[2];
    const float* b_first = (const float*)d_in[3];
    const float* W_dil   = (const float*)d_in[4];
    const float* b_dil   = (const float*)d_in[5];
    const float* W_c     = (const float*)d_in[6];
    const float* b_c     = (const float*)d_in[7];
    const float* W_skip  = (const float*)d_in[8];
    const float* b_skip  = (const float*)d_in[9];
    const float* W_out   = (const float*)d_in[10];
    const float* b_out   = (const float*)d_in[11];
    const float* W_last1 = (const float*)d_in[12];
    const float* b_last1 = (const float*)d_in[13];
    const float* W_last2 = (const float*)d_in[14];
    const float* b_last2 = (const float*)d_in[15];
    float* out = (float*)d_out;

    cudaFuncSetAttribute(first_kernel,  cudaFuncAttributeMaxDynamicSharedMemorySize, FIRST_SMEM);
    cudaFuncSetAttribute(gate_kernel,   cudaFuncAttributeMaxDynamicSharedMemorySize, GATE_SMEM);
    cudaFuncSetAttribute(skipout_kernel,cudaFuncAttributeMaxDynamicSharedMemorySize, SKIPOUT_SMEM);
    cudaFuncSetAttribute(dense256_kernel,cudaFuncAttributeMaxDynamicSharedMemorySize, DENSE_SMEM);

    int dev = 0;
    cudaGetDevice(&dev);
    int sm_count = 148;
    cudaDeviceGetAttribute(&sm_count, cudaDevAttrMultiProcessorCount, dev);
    int grid_p = sm_count < 1024 ? sm_count : 1024;

    first_kernel<<<grid_p, 256, FIRST_SMEM>>>(x, W_first, b_first);

    for (int l = 0; l < 20; l++) {
        int dil = 1 << (l % 10);
        int hsel = l & 1;   // layer l reads g_h[hsel], writes g_h[1-hsel]
        gate_kernel<<<grid_p, 512, GATE_SMEM>>>(l, dil, hsel, c,
                                                W_dil, b_dil, W_c, b_c);
        skipout_kernel<<<grid_p, 512, SKIPOUT_SMEM>>>(l, hsel,
                                                      W_skip, b_skip, W_out, b_out);
    }

    dense256_kernel<<<grid_p, 512, DENSE_SMEM>>>(0, out, W_last1, b_last1);
    dense256_kernel<<<grid_p, 512, DENSE_SMEM>>>(1, out, W_last2, b_last2);
}